// round 6
// baseline (speedup 1.0000x reference)
#include <cuda_runtime.h>
#include <cstdint>

#define N_NODES 50000
#define IN_FEAT 512
#define OUT_FEAT 256
#define N_EDGES 1600000
#define ALPHA 0.2f

// smem layout: [0, 200000): s_src floats; then w staging (2 x 2048 B)
#define SMEM_S_BYTES (N_NODES * 4)
#define SMEM_BYTES   (SMEM_S_BYTES + 2 * (IN_FEAT / 4) * 16)

// Scratch (allocation-free rule: __device__ globals).
__device__ float4 g_w_src4[IN_FEAT / 4];
__device__ float4 g_w_tgt4[IN_FEAT / 4];
__device__ float g_s_src[N_NODES];
__device__ float g_s_tgt[N_NODES];

// Monotonic-ticket grid barrier (no reset; safe across graph replays).
__device__ unsigned g_bar = 0;

__device__ __forceinline__ float dot4(float4 a, float4 b) {
    return a.x * b.x + a.y * b.y + a.z * b.z + a.w * b.w;
}

__device__ __forceinline__ void grid_sync(unsigned nblocks) {
    __syncthreads();
    if (threadIdx.x == 0) {
        __threadfence();
        unsigned ticket = atomicAdd(&g_bar, 1u);
        unsigned target = (ticket / nblocks + 1u) * nblocks;
        while (*(volatile unsigned*)&g_bar < target) { }
        __threadfence();
    }
    __syncthreads();
}

// ---------------------------------------------------------------------------
// Fused persistent kernel, 1 block per SM, 1024 threads.
// Phase A: w = W @ a  -> barrier -> Phase B: node scores -> barrier ->
// Phase C: smem-gather(s_src) + l1tex-gather(s_tgt) + leaky_relu.
// ---------------------------------------------------------------------------
__global__ __launch_bounds__(1024, 1) void fused_gat_kernel(
    const float* __restrict__ h,
    const int*   __restrict__ edge_list,
    const float* __restrict__ W,
    const float* __restrict__ attn_w,
    float*       __restrict__ out,
    int nblocks)
{
    extern __shared__ char smem_raw[];
    float*  sh_s  = reinterpret_cast<float*>(smem_raw);
    float4* sh_ws = reinterpret_cast<float4*>(smem_raw + SMEM_S_BYTES);
    float4* sh_wt = sh_ws + (IN_FEAT / 4);

    const int tid  = threadIdx.x;
    const int lane = tid & 31;
    const int wid  = tid >> 5;                    // 0..31
    const int gw   = blockIdx.x * 32 + wid;       // global warp id
    const int nwarps   = nblocks * 32;
    const int nthreads = nblocks * 1024;

    // ---------------- Phase A: w_src = W @ a_src, w_tgt = W @ a_tgt --------
    if (gw < IN_FEAT) {
        const float4* wrow4 = reinterpret_cast<const float4*>(W + (size_t)gw * OUT_FEAT);
        const float4* as4   = reinterpret_cast<const float4*>(attn_w);
        const float4* at4   = reinterpret_cast<const float4*>(attn_w + OUT_FEAT);

        float4 w0 = wrow4[lane];
        float4 w1 = wrow4[32 + lane];
        float acc_s = dot4(w0, as4[lane]) + dot4(w1, as4[32 + lane]);
        float acc_t = dot4(w0, at4[lane]) + dot4(w1, at4[32 + lane]);
#pragma unroll
        for (int off = 16; off > 0; off >>= 1) {
            acc_s += __shfl_xor_sync(0xffffffffu, acc_s, off);
            acc_t += __shfl_xor_sync(0xffffffffu, acc_t, off);
        }
        if (lane == 0) {
            reinterpret_cast<float*>(g_w_src4)[gw] = acc_s;
            reinterpret_cast<float*>(g_w_tgt4)[gw] = acc_t;
        }
    }

    grid_sync(nblocks);

    // Stage w vectors into shared
    for (int i = tid; i < IN_FEAT / 4; i += 1024) {
        sh_ws[i] = g_w_src4[i];
        sh_wt[i] = g_w_tgt4[i];
    }
    __syncthreads();

    // ---------------- Phase B: node scores (warp per node, grid-stride) ----
    for (int node = gw; node < N_NODES; node += nwarps) {
        const float4* h4 = reinterpret_cast<const float4*>(h + (size_t)node * IN_FEAT);

        float4 hv0 = h4[lane];
        float4 hv1 = h4[32 + lane];
        float4 hv2 = h4[64 + lane];
        float4 hv3 = h4[96 + lane];

        float acc_s = dot4(hv0, sh_ws[lane])      + dot4(hv1, sh_ws[32 + lane]) +
                      dot4(hv2, sh_ws[64 + lane]) + dot4(hv3, sh_ws[96 + lane]);
        float acc_t = dot4(hv0, sh_wt[lane])      + dot4(hv1, sh_wt[32 + lane]) +
                      dot4(hv2, sh_wt[64 + lane]) + dot4(hv3, sh_wt[96 + lane]);

        // Split-half reduction: lo 16 lanes reduce acc_s, hi 16 reduce acc_t.
        float os = __shfl_xor_sync(0xffffffffu, acc_s, 16);
        float ot = __shfl_xor_sync(0xffffffffu, acc_t, 16);
        float v = (lane < 16) ? (acc_s + os) : (acc_t + ot);
#pragma unroll
        for (int off = 8; off > 0; off >>= 1)
            v += __shfl_xor_sync(0xffffffffu, v, off);
        if (lane == 0)  g_s_src[node] = v;
        if (lane == 16) g_s_tgt[node] = v;
    }

    grid_sync(nblocks);

    // ---------------- Fill smem with the full s_src array ------------------
    {
        const float4* gsrc4 = reinterpret_cast<const float4*>(g_s_src);
        float4* shs4 = reinterpret_cast<float4*>(sh_s);
        for (int i = tid; i < N_NODES / 4; i += 1024)   // 12500 float4
            shs4[i] = gsrc4[i];
    }
    __syncthreads();

    // ---------------- Phase C: edge gather + leaky_relu (4 edges/thread) ---
    const int n4 = N_EDGES / 4;
    const int4*  src4 = reinterpret_cast<const int4*>(edge_list);
    const int4*  tgt4 = reinterpret_cast<const int4*>(edge_list + N_EDGES);
    float4*      out4 = reinterpret_cast<float4*>(out);

    for (int k4 = blockIdx.x * 1024 + tid; k4 < n4; k4 += nthreads) {
        int4 s = src4[k4];
        int4 t = tgt4[k4];

        // s_src from shared (LDS random ~4 cyc/warp), s_tgt via L1/L2.
        float e0 = sh_s[s.x] + __ldg(&g_s_tgt[t.x]);
        float e1 = sh_s[s.y] + __ldg(&g_s_tgt[t.y]);
        float e2 = sh_s[s.z] + __ldg(&g_s_tgt[t.z]);
        float e3 = sh_s[s.w] + __ldg(&g_s_tgt[t.w]);

        float4 r;
        r.x = (e0 > 0.f) ? e0 : ALPHA * e0;
        r.y = (e1 > 0.f) ? e1 : ALPHA * e1;
        r.z = (e2 > 0.f) ? e2 : ALPHA * e2;
        r.w = (e3 > 0.f) ? e3 : ALPHA * e3;
        out4[k4] = r;
    }
}

// ---------------------------------------------------------------------------
extern "C" void kernel_launch(void* const* d_in, const int* in_sizes, int n_in,
                              void* d_out, int out_size) {
    const float* h         = (const float*)d_in[0];
    const int*   edge_list = (const int*)d_in[1];
    const float* W         = (const float*)d_in[2];
    const float* attn_w    = (const float*)d_in[3];
    float* out = (float*)d_out;

    // Opt in to large dynamic smem (idempotent, capture-safe: no work enqueued)
    cudaFuncSetAttribute(fused_gat_kernel,
                         cudaFuncAttributeMaxDynamicSharedMemorySize, SMEM_BYTES);

    int dev = 0;
    cudaGetDevice(&dev);
    int sms = 148;
    cudaDeviceGetAttribute(&sms, cudaDevAttrMultiProcessorCount, dev);
    int occ = 1;
    cudaOccupancyMaxActiveBlocksPerMultiprocessor(&occ, fused_gat_kernel, 1024, SMEM_BYTES);
    if (occ < 1) occ = 1;                 // 204 KB smem -> expect exactly 1
    int nblocks = sms * occ;
    if (nblocks < 16) nblocks = 16;       // phase A needs >= 512 warps

    fused_gat_kernel<<<nblocks, 1024, SMEM_BYTES>>>(h, edge_list, W, attn_w, out, nblocks);
}

// round 7
// speedup vs baseline: 1.2229x; 1.2229x over previous
#include <cuda_runtime.h>
#include <cstdint>

#define N_NODES 50000
#define IN_FEAT 512
#define OUT_FEAT 256
#define N_EDGES 1600000
#define ALPHA 0.2f

// Scratch (allocation-free rule: __device__ globals).
__device__ float4 g_w_src4[IN_FEAT / 4];
__device__ float4 g_w_tgt4[IN_FEAT / 4];
__device__ float g_s_src[N_NODES];
__device__ float g_s_tgt[N_NODES];

// Monotonic-ticket grid barrier (no reset; safe across graph replays).
__device__ unsigned g_bar = 0;

__device__ __forceinline__ float dot4(float4 a, float4 b) {
    return a.x * b.x + a.y * b.y + a.z * b.z + a.w * b.w;
}

__device__ __forceinline__ void grid_sync(unsigned nblocks) {
    __syncthreads();
    if (threadIdx.x == 0) {
        __threadfence();
        unsigned ticket = atomicAdd(&g_bar, 1u);
        unsigned target = (ticket / nblocks + 1u) * nblocks;
        while (*(volatile unsigned*)&g_bar < target) { }
        __threadfence();
    }
    __syncthreads();
}

// ---------------------------------------------------------------------------
// Fused persistent kernel: A -> barrier -> B (2 nodes/warp-iter) -> barrier -> C
// ---------------------------------------------------------------------------
__global__ __launch_bounds__(256) void fused_gat_kernel(
    const float* __restrict__ h,
    const int*   __restrict__ edge_list,
    const float* __restrict__ W,
    const float* __restrict__ attn_w,
    float*       __restrict__ out,
    int nblocks)
{
    __shared__ float4 sh_ws[IN_FEAT / 4];
    __shared__ float4 sh_wt[IN_FEAT / 4];

    const int tid  = threadIdx.x;
    const int lane = tid & 31;
    const int wid  = tid >> 5;                    // 0..7
    const int gw   = blockIdx.x * 8 + wid;        // global warp id
    const int nwarps   = nblocks * 8;
    const int nthreads = nblocks * 256;

    // ---------------- Phase A: w_src = W @ a_src, w_tgt = W @ a_tgt --------
    if (gw < IN_FEAT) {
        const float4* wrow4 = reinterpret_cast<const float4*>(W + (size_t)gw * OUT_FEAT);
        const float4* as4   = reinterpret_cast<const float4*>(attn_w);
        const float4* at4   = reinterpret_cast<const float4*>(attn_w + OUT_FEAT);

        float4 w0 = wrow4[lane];
        float4 w1 = wrow4[32 + lane];
        float acc_s = dot4(w0, as4[lane]) + dot4(w1, as4[32 + lane]);
        float acc_t = dot4(w0, at4[lane]) + dot4(w1, at4[32 + lane]);
#pragma unroll
        for (int off = 16; off > 0; off >>= 1) {
            acc_s += __shfl_xor_sync(0xffffffffu, acc_s, off);
            acc_t += __shfl_xor_sync(0xffffffffu, acc_t, off);
        }
        if (lane == 0) {
            reinterpret_cast<float*>(g_w_src4)[gw] = acc_s;
            reinterpret_cast<float*>(g_w_tgt4)[gw] = acc_t;
        }
    }

    grid_sync(nblocks);

    // Stage w vectors into shared (4 KB)
    for (int i = tid; i < IN_FEAT / 4; i += 256) {
        sh_ws[i] = g_w_src4[i];
        sh_wt[i] = g_w_tgt4[i];
    }
    __syncthreads();

    // ---------------- Phase B: node scores, 2 nodes per warp-iteration -----
    // 8 independent LDG.128 issued up front -> ~2x memory-level parallelism.
    for (int n0 = gw * 2; n0 < N_NODES; n0 += nwarps * 2) {
        const int n1 = n0 + 1;
        const float4* h4a = reinterpret_cast<const float4*>(h + (size_t)n0 * IN_FEAT);

        float4 a0 = h4a[lane];
        float4 a1 = h4a[32 + lane];
        float4 a2 = h4a[64 + lane];
        float4 a3 = h4a[96 + lane];

        float4 b0, b1, b2, b3;
        if (n1 < N_NODES) {
            const float4* h4b = reinterpret_cast<const float4*>(h + (size_t)n1 * IN_FEAT);
            b0 = h4b[lane];
            b1 = h4b[32 + lane];
            b2 = h4b[64 + lane];
            b3 = h4b[96 + lane];
        } else {
            b0 = b1 = b2 = b3 = make_float4(0.f, 0.f, 0.f, 0.f);
        }

        float4 w0 = sh_ws[lane],      w1 = sh_ws[32 + lane];
        float4 w2 = sh_ws[64 + lane], w3 = sh_ws[96 + lane];
        float4 t0 = sh_wt[lane],      t1 = sh_wt[32 + lane];
        float4 t2 = sh_wt[64 + lane], t3 = sh_wt[96 + lane];

        float as0 = dot4(a0, w0) + dot4(a1, w1) + dot4(a2, w2) + dot4(a3, w3);
        float at0 = dot4(a0, t0) + dot4(a1, t1) + dot4(a2, t2) + dot4(a3, t3);
        float as1 = dot4(b0, w0) + dot4(b1, w1) + dot4(b2, w2) + dot4(b3, w3);
        float at1 = dot4(b0, t0) + dot4(b1, t1) + dot4(b2, t2) + dot4(b3, t3);

        // Split-half reduction over pairs: lanes<16 carry node0 (s,t packed),
        // Reduce all four values: pack as (as0,at0) in lo-half, (as1,at1) hi-half.
        float xs = __shfl_xor_sync(0xffffffffu, as0, 16);
        float xt = __shfl_xor_sync(0xffffffffu, at0, 16);
        float ys = __shfl_xor_sync(0xffffffffu, as1, 16);
        float yt = __shfl_xor_sync(0xffffffffu, at1, 16);
        // u reduces node0's s (lo) / t (hi); v reduces node1's s (lo) / t (hi)
        float u = (lane < 16) ? (as0 + xs) : (at0 + xt);
        float v = (lane < 16) ? (as1 + ys) : (at1 + yt);
#pragma unroll
        for (int off = 8; off > 0; off >>= 1) {
            u += __shfl_xor_sync(0xffffffffu, u, off);
            v += __shfl_xor_sync(0xffffffffu, v, off);
        }
        if (lane == 0)  g_s_src[n0] = u;
        if (lane == 16) g_s_tgt[n0] = u;
        if (n1 < N_NODES) {
            if (lane == 0)  g_s_src[n1] = v;
            if (lane == 16) g_s_tgt[n1] = v;
        }
    }

    grid_sync(nblocks);

    // ---------------- Phase C: edge gather + leaky_relu (4 edges/thread) ---
    const int n4 = N_EDGES / 4;
    const int4*  src4 = reinterpret_cast<const int4*>(edge_list);
    const int4*  tgt4 = reinterpret_cast<const int4*>(edge_list + N_EDGES);
    float4*      out4 = reinterpret_cast<float4*>(out);

    for (int k4 = blockIdx.x * 256 + tid; k4 < n4; k4 += nthreads) {
        int4 s = src4[k4];
        int4 t = tgt4[k4];

        float e0 = __ldg(&g_s_src[s.x]) + __ldg(&g_s_tgt[t.x]);
        float e1 = __ldg(&g_s_src[s.y]) + __ldg(&g_s_tgt[t.y]);
        float e2 = __ldg(&g_s_src[s.z]) + __ldg(&g_s_tgt[t.z]);
        float e3 = __ldg(&g_s_src[s.w]) + __ldg(&g_s_tgt[t.w]);

        float4 r;
        r.x = (e0 > 0.f) ? e0 : ALPHA * e0;
        r.y = (e1 > 0.f) ? e1 : ALPHA * e1;
        r.z = (e2 > 0.f) ? e2 : ALPHA * e2;
        r.w = (e3 > 0.f) ? e3 : ALPHA * e3;
        out4[k4] = r;
    }
}

// ---------------------------------------------------------------------------
extern "C" void kernel_launch(void* const* d_in, const int* in_sizes, int n_in,
                              void* d_out, int out_size) {
    const float* h         = (const float*)d_in[0];
    const int*   edge_list = (const int*)d_in[1];
    const float* W         = (const float*)d_in[2];
    const float* attn_w    = (const float*)d_in[3];
    float* out = (float*)d_out;

    int dev = 0;
    cudaGetDevice(&dev);
    int sms = 148;
    cudaDeviceGetAttribute(&sms, cudaDevAttrMultiProcessorCount, dev);
    int occ = 1;
    cudaOccupancyMaxActiveBlocksPerMultiprocessor(&occ, fused_gat_kernel, 256, 0);
    if (occ < 1) occ = 1;
    int nblocks = sms * occ;           // exactly one co-resident wave
    if (nblocks < 64) nblocks = 64;    // phase A needs >= 512 warps

    fused_gat_kernel<<<nblocks, 256>>>(h, edge_list, W, attn_w, out, nblocks);
}